// round 15
// baseline (speedup 1.0000x reference)
#include <cuda_runtime.h>
#include <cuda_bf16.h>
#include <mma.h>
#include <math.h>
#include <stdint.h>

using namespace nvcuda;

#define NN 50000
#define NE 800000
#define DD 128
#define OUT_ELEMS (NN * DD)
#define BM 128
#define GEMM_BLOCKS ((NN + BM - 1) / BM)
#define SCAN_B ((NN + 255) / 256)
#define EPT 4
#define EDGE_BLOCKS ((NE / EPT + 255) / 256)
#define ALD 72
#define BLD 136
#define AS_BYTES (2 * 2 * 128 * ALD * 2)            // 73728
#define BS_BYTES (2 * 2 * 64 * BLD * 2)             // 69632
#define EMB_BYTES (2 * 128 * BLD * 2)               // 69632
#define SMEM_G0 (AS_BYTES + BS_BYTES)               // 143360
#define SMEM_G1 (AS_BYTES + BS_BYTES + EMB_BYTES)   // 212992

// ---------------- device scratch (zero at load; every call restores zeros) --------
__device__ __align__(16) float g_h[NN * DD];
__device__ __align__(16) float g_emb[NN * DD];     // only used when lead < 0
__device__ __align__(16) unsigned short g_meanH[NN * DD];
__device__ __align__(16) unsigned short g_meanL[NN * DD];
__device__ __align__(16) unsigned short g_xH[NN * DD];
__device__ __align__(16) unsigned short g_xL[NN * DD];
__device__ __align__(16) unsigned short g_hH[NN * DD];
__device__ __align__(16) unsigned short g_hL[NN * DD];
__device__ int   g_deg[NN];
__device__ int   g_off[NN + 1];
__device__ int   g_cur[NN];
__device__ int   g_col[NE];
__device__ unsigned char g_yb[NN];
__device__ float g_lp;
__device__ float g_ln;
__device__ int   g_npos;
__device__ int   g_done;
__device__ unsigned long long g_lb[SCAN_B];
__device__ __align__(16) unsigned short g_Bimg[5][2][DD * DD];

// ---------------- fp32 -> bf16 hi/lo packing ----------------
__device__ __forceinline__ void split4(float4 v, uint2& hi, uint2& lo) {
    __nv_bfloat162 h0 = __float22bfloat162_rn(make_float2(v.x, v.y));
    __nv_bfloat162 h1 = __float22bfloat162_rn(make_float2(v.z, v.w));
    float2 f0 = __bfloat1622float2(h0);
    float2 f1 = __bfloat1622float2(h1);
    __nv_bfloat162 l0 = __float22bfloat162_rn(make_float2(v.x - f0.x, v.y - f0.y));
    __nv_bfloat162 l1 = __float22bfloat162_rn(make_float2(v.z - f1.x, v.w - f1.y));
    hi = make_uint2(*(uint32_t*)&h0, *(uint32_t*)&h1);
    lo = make_uint2(*(uint32_t*)&l0, *(uint32_t*)&l1);
}

// ---------------- cp.async helpers ----------------
__device__ __forceinline__ void cpa16(uint32_t saddr, const void* g, int szr) {
    asm volatile("cp.async.cg.shared.global [%0], [%1], 16, %2;"
                 :: "r"(saddr), "l"(g), "r"(szr) : "memory");
}
#define CPA_COMMIT() asm volatile("cp.async.commit_group;" ::: "memory")
#define CPA_WAIT0()  asm volatile("cp.async.wait_group 0;" ::: "memory")
__device__ __forceinline__ uint32_t s_u32(const void* p) {
    return (uint32_t)__cvta_generic_to_shared(p);
}

// ---------------- per-block dtype detection ----------------
__device__ __forceinline__ int detect_e64(const void* edge) {
    __shared__ int s64;
    if (threadIdx.x == 0) s64 = 1;
    __syncthreads();
    if (threadIdx.x < 256) {
        long long v = ((const long long*)edge)[threadIdx.x];
        if (v < 0 || v >= NN) atomicAnd(&s64, 0);
    }
    __syncthreads();
    return s64;
}

__device__ __forceinline__ int edge_at(const void* edge, int idx, int e64) {
    if (e64) return (int)((const long long*)edge)[idx];
    return ((const int*)edge)[idx];
}

// ---------------- k_prep: detect + y + weight split + x images + degree ----------
__global__ void k_prep(const void* __restrict__ yv, const void* __restrict__ edge,
                       const float* __restrict__ x,
                       const float* __restrict__ W0, const float* __restrict__ W1,
                       const float* __restrict__ W2, const float* __restrict__ W3,
                       const float* __restrict__ W4) {
    __shared__ int s32;
    if (threadIdx.x == 0) s32 = 1;
    int e64 = detect_e64(edge);
    if (threadIdx.x < 64) {
        unsigned int w = ((const unsigned int*)yv)[threadIdx.x];
        if (w > 1u) atomicAnd(&s32, 0);
    }
    __syncthreads();
    int y32 = s32;

    int i = blockIdx.x * blockDim.x + threadIdx.x;
    int nth = gridDim.x * blockDim.x;
    int v = 0;
    if (i < NN) {
        if (y32) v = (((const int*)yv)[i] != 0) ? 1 : 0;
        else     v = (((const unsigned char*)yv)[i] != 0) ? 1 : 0;
        g_yb[i] = (unsigned char)v;
    }
    #pragma unroll
    for (int o = 16; o; o >>= 1) v += __shfl_down_sync(0xffffffffu, v, o);
    if ((threadIdx.x & 31) == 0 && v) atomicAdd(&g_npos, v);

    if (i < 5 * DD * DD) {
        int w = i / (DD * DD);
        int r = i % (DD * DD);
        const float* Wm = (w == 0) ? W0 : (w == 1) ? W1 : (w == 2) ? W2 : (w == 3) ? W3 : W4;
        float val = Wm[r];
        __nv_bfloat16 hi = __float2bfloat16(val);
        g_Bimg[w][0][r] = __bfloat16_as_ushort(hi);
        g_Bimg[w][1][r] = __bfloat16_as_ushort(__float2bfloat16(val - __bfloat162float(hi)));
    }

    // x hi/lo images (grid-stride over 1.6M float4)
    for (int q = i; q < NN * DD / 4; q += nth) {
        float4 vv = ((const float4*)x)[q];
        uint2 hi, lo;
        split4(vv, hi, lo);
        *(uint2*)&g_xH[q * 4] = hi;
        *(uint2*)&g_xL[q * 4] = lo;
    }

    int base = i * EPT;
    int d[EPT];
    #pragma unroll
    for (int j = 0; j < EPT; j++)
        d[j] = (base + j < NE) ? edge_at(edge, NE + base + j, e64) : -1;
    #pragma unroll
    for (int j = 0; j < EPT; j++)
        if (d[j] >= 0 && d[j] < NN) atomicAdd(&g_deg[d[j]], 1);
}

// ---------------- decoupled-lookback scan ----------------
__global__ void k_scan() {
    __shared__ int sh[256];
    __shared__ int s_ex;
    int b = blockIdx.x, t = threadIdx.x;
    int i = b * 256 + t;
    int v = (i < NN) ? g_deg[i] : 0;
    sh[t] = v;
    __syncthreads();
    for (int o = 1; o < 256; o <<= 1) {
        int add = (t >= o) ? sh[t - o] : 0;
        __syncthreads();
        sh[t] += add;
        __syncthreads();
    }
    int T = sh[255];
    if (t == 0) {
        if (b == 0) {
            atomicExch(&g_lb[0], (2ULL << 32) | (unsigned)T);
            s_ex = 0;
        } else {
            atomicExch(&g_lb[b], (1ULL << 32) | (unsigned)T);
            int ex = 0;
            for (int j = b - 1; j >= 0;) {
                unsigned long long w;
                do { w = atomicAdd(&g_lb[j], 0ULL); } while ((w >> 32) == 0ULL);
                if ((w >> 32) == 2ULL) { ex += (int)(unsigned)w; break; }
                ex += (int)(unsigned)w;
                j--;
            }
            atomicExch(&g_lb[b], (2ULL << 32) | (unsigned)(ex + T));
            s_ex = ex;
        }
    }
    __syncthreads();
    int ex = s_ex;
    if (i < NN) {
        int off = ex + sh[t] - v;
        g_off[i] = off;
        g_cur[i] = off;
        g_deg[i] = 0;
    }
    if (b == SCAN_B - 1 && t == 0) g_off[NN] = ex + T;
}

// ---------------- CSR fill ----------------
__global__ void k_fill(const void* __restrict__ edge) {
    int e64 = detect_e64(edge);
    int i = blockIdx.x * blockDim.x + threadIdx.x;
    if (i < SCAN_B) g_lb[i] = 0ULL;
    int base = i * EPT;
    int s[EPT], d[EPT];
    #pragma unroll
    for (int j = 0; j < EPT; j++) {
        if (base + j < NE) {
            d[j] = edge_at(edge, NE + base + j, e64);
            s[j] = edge_at(edge, base + j, e64);
        } else { d[j] = -1; s[j] = 0; }
    }
    #pragma unroll
    for (int j = 0; j < EPT; j++) {
        if (d[j] >= 0 && d[j] < NN && s[j] >= 0 && s[j] < NN) {
            int p = atomicAdd(&g_cur[d[j]], 1);
            g_col[p] = s[j];
        }
    }
}

// ---------------- mean aggregation: 1 warp/node; writes bf16 hi/lo images ---------
template <int SRC>
__global__ void k_mean(const float* __restrict__ feat) {
    int node = blockIdx.x * 8 + (threadIdx.x >> 5);
    int lane = threadIdx.x & 31;
    if (node >= NN) return;
    const float4* __restrict__ f = (const float4*)((SRC == 0) ? feat : (const float*)g_h);
    int s = g_off[node], e = g_off[node + 1];
    float4 acc = make_float4(0.f, 0.f, 0.f, 0.f);
    int k = s;
    for (; k + 8 <= e; k += 8) {
        int c[8];
        #pragma unroll
        for (int j = 0; j < 8; j++) c[j] = __ldg(&g_col[k + j]);
        float4 v[8];
        #pragma unroll
        for (int j = 0; j < 8; j++) v[j] = __ldg(&f[(size_t)c[j] * 32 + lane]);
        acc.x += ((v[0].x + v[1].x) + (v[2].x + v[3].x)) + ((v[4].x + v[5].x) + (v[6].x + v[7].x));
        acc.y += ((v[0].y + v[1].y) + (v[2].y + v[3].y)) + ((v[4].y + v[5].y) + (v[6].y + v[7].y));
        acc.z += ((v[0].z + v[1].z) + (v[2].z + v[3].z)) + ((v[4].z + v[5].z) + (v[6].z + v[7].z));
        acc.w += ((v[0].w + v[1].w) + (v[2].w + v[3].w)) + ((v[4].w + v[5].w) + (v[6].w + v[7].w));
    }
    for (; k < e; k++) {
        float4 v = __ldg(&f[(size_t)__ldg(&g_col[k]) * 32 + lane]);
        acc.x += v.x; acc.y += v.y; acc.z += v.z; acc.w += v.w;
    }
    float inv = 1.f / fmaxf((float)(e - s), 1.f);
    float4 m = make_float4(acc.x * inv, acc.y * inv, acc.z * inv, acc.w * inv);
    uint2 hi, lo;
    split4(m, hi, lo);
    size_t o = (size_t)node * DD + lane * 4;
    *(uint2*)&g_meanH[o] = hi;
    *(uint2*)&g_meanL[o] = lo;
}

// ---------------- cp.async double-buffered WMMA bf16x3 GEMM, K=64 chunks ----------
typedef wmma::fragment<wmma::accumulator, 16, 16, 16, float> AccFrag;

__device__ __forceinline__ __nv_bfloat16* as_ptr(char* sdyn, int buf, int hl) {
    return (__nv_bfloat16*)sdyn + (size_t)(buf * 2 + hl) * 128 * ALD;
}
__device__ __forceinline__ __nv_bfloat16* bs_ptr(char* sdyn, int buf, int hl) {
    return (__nv_bfloat16*)(sdyn + AS_BYTES) + (size_t)(buf * 2 + hl) * 64 * BLD;
}
__device__ __forceinline__ __nv_bfloat16* emb_ptr(char* sdyn, int hl) {
    return (__nv_bfloat16*)(sdyn + AS_BYTES + BS_BYTES) + (size_t)hl * 128 * BLD;
}

// issue one K=64 chunk: A hi/lo images + B hi/lo images, 8 cp.async per thread
__device__ __forceinline__ void issue_chunk(char* sdyn, int buf,
                                            const unsigned short* __restrict__ AH,
                                            const unsigned short* __restrict__ AL,
                                            int wsel, int c, int m0, int tid) {
    __nv_bfloat16* Ah = as_ptr(sdyn, buf, 0);
    __nv_bfloat16* Al = as_ptr(sdyn, buf, 1);
    #pragma unroll
    for (int it = 0; it < 2; it++) {
        int id = tid + it * 512;          // 1024 pieces: row 0..127, p 0..7
        int row = id >> 3, p = id & 7;
        int gm = m0 + row;
        int ok = (gm < NN) ? 16 : 0;
        size_t go = ok ? ((size_t)gm * DD + c * 64 + p * 8) : 0;
        uint32_t so = (uint32_t)(row * ALD + p * 8) * 2;
        cpa16(s_u32(Ah) + so, AH + go, ok);
        cpa16(s_u32(Al) + so, AL + go, ok);
    }
    #pragma unroll
    for (int hl = 0; hl < 2; hl++) {
        __nv_bfloat16* B = bs_ptr(sdyn, buf, hl);
        #pragma unroll
        for (int half = 0; half < 2; half++) {
            int id = tid + half * 512;    // 1024 pieces: k 0..63, p 0..15
            int k = id >> 4, p = id & 15;
            cpa16(s_u32(B) + (uint32_t)(k * BLD + p * 8) * 2,
                  &g_Bimg[wsel][hl][(c * 64 + k) * DD + p * 8], 16);
        }
    }
    CPA_COMMIT();
}

// issue decoder B-only chunk (4 cp.async per thread)
__device__ __forceinline__ void issue_bchunk(char* sdyn, int buf, int c, int tid) {
    #pragma unroll
    for (int hl = 0; hl < 2; hl++) {
        __nv_bfloat16* B = bs_ptr(sdyn, buf, hl);
        #pragma unroll
        for (int half = 0; half < 2; half++) {
            int id = tid + half * 512;
            int k = id >> 4, p = id & 15;
            cpa16(s_u32(B) + (uint32_t)(k * BLD + p * 8) * 2,
                  &g_Bimg[4][hl][(c * 64 + k) * DD + p * 8], 16);
        }
    }
    CPA_COMMIT();
}

__device__ __forceinline__ void mma_chunk(char* sdyn, int buf,
                                          AccFrag (&acc)[2][2], int warp_m, int warp_n) {
    __nv_bfloat16* Ah = as_ptr(sdyn, buf, 0);
    __nv_bfloat16* Al = as_ptr(sdyn, buf, 1);
    __nv_bfloat16* Bh = bs_ptr(sdyn, buf, 0);
    __nv_bfloat16* Bl = bs_ptr(sdyn, buf, 1);
    #pragma unroll
    for (int ks = 0; ks < 4; ks++) {
        wmma::fragment<wmma::matrix_a, 16, 16, 16, __nv_bfloat16, wmma::row_major> a_hi[2], a_lo[2];
        #pragma unroll
        for (int mt = 0; mt < 2; mt++) {
            int mr = (warp_m * 32 + mt * 16) * ALD + ks * 16;
            wmma::load_matrix_sync(a_hi[mt], &Ah[mr], ALD);
            wmma::load_matrix_sync(a_lo[mt], &Al[mr], ALD);
        }
        #pragma unroll
        for (int nt = 0; nt < 2; nt++) {
            int nb = warp_n * 32 + nt * 16;
            wmma::fragment<wmma::matrix_b, 16, 16, 16, __nv_bfloat16, wmma::row_major> b_hi, b_lo;
            wmma::load_matrix_sync(b_hi, &Bh[ks * 16 * BLD + nb], BLD);
            wmma::load_matrix_sync(b_lo, &Bl[ks * 16 * BLD + nb], BLD);
            #pragma unroll
            for (int mt = 0; mt < 2; mt++) {
                wmma::mma_sync(acc[mt][nt], a_hi[mt], b_hi, acc[mt][nt]);
                wmma::mma_sync(acc[mt][nt], a_hi[mt], b_lo, acc[mt][nt]);
                wmma::mma_sync(acc[mt][nt], a_lo[mt], b_hi, acc[mt][nt]);
            }
        }
    }
}

// decoder mma: A frags from smem emb image (BLD leading dim), K=64 chunk c
__device__ __forceinline__ void mma_dec(char* sdyn, int buf, int c,
                                        AccFrag (&acc)[2][2], int warp_m, int warp_n) {
    __nv_bfloat16* Eh = emb_ptr(sdyn, 0);
    __nv_bfloat16* El = emb_ptr(sdyn, 1);
    __nv_bfloat16* Bh = bs_ptr(sdyn, buf, 0);
    __nv_bfloat16* Bl = bs_ptr(sdyn, buf, 1);
    #pragma unroll
    for (int ks = 0; ks < 4; ks++) {
        wmma::fragment<wmma::matrix_a, 16, 16, 16, __nv_bfloat16, wmma::row_major> a_hi[2], a_lo[2];
        #pragma unroll
        for (int mt = 0; mt < 2; mt++) {
            int mr = (warp_m * 32 + mt * 16) * BLD + c * 64 + ks * 16;
            wmma::load_matrix_sync(a_hi[mt], &Eh[mr], BLD);
            wmma::load_matrix_sync(a_lo[mt], &El[mr], BLD);
        }
        #pragma unroll
        for (int nt = 0; nt < 2; nt++) {
            int nb = warp_n * 32 + nt * 16;
            wmma::fragment<wmma::matrix_b, 16, 16, 16, __nv_bfloat16, wmma::row_major> b_hi, b_lo;
            wmma::load_matrix_sync(b_hi, &Bh[ks * 16 * BLD + nb], BLD);
            wmma::load_matrix_sync(b_lo, &Bl[ks * 16 * BLD + nb], BLD);
            #pragma unroll
            for (int mt = 0; mt < 2; mt++) {
                wmma::mma_sync(acc[mt][nt], a_hi[mt], b_hi, acc[mt][nt]);
                wmma::mma_sync(acc[mt][nt], a_hi[mt], b_lo, acc[mt][nt]);
                wmma::mma_sync(acc[mt][nt], a_lo[mt], b_hi, acc[mt][nt]);
            }
        }
    }
}

// pipelined accumulation over 2 sources x 2 K-chunks = 4 iterations
__device__ __forceinline__ void gemm_pipeline(
    char* sdyn,
    const unsigned short* __restrict__ A0H, const unsigned short* __restrict__ A0L, int wsel0,
    const unsigned short* __restrict__ A1H, const unsigned short* __restrict__ A1L, int wsel1,
    int m0, AccFrag (&acc)[2][2], int tid, int warp_m, int warp_n) {
    issue_chunk(sdyn, 0, A0H, A0L, wsel0, 0, m0, tid);
    const int T = 4;
    for (int t = 0; t < T; t++) {
        CPA_WAIT0();
        __syncthreads();          // chunk t visible to all; all warps done with mma(t-1)
        if (t + 1 < T) {
            int nsrc = (t + 1) >> 1;
            issue_chunk(sdyn, (t + 1) & 1,
                        nsrc ? A1H : A0H, nsrc ? A1L : A0L,
                        nsrc ? wsel1 : wsel0, (t + 1) & 1, m0, tid);
        }
        mma_chunk(sdyn, t & 1, acc, warp_m, warp_n);
    }
    __syncthreads();
}

// store all 16 warps' acc frags into one 128 x BLD fp32 smem tile
__device__ __forceinline__ void store_frags(float* buf, AccFrag (&acc)[2][2],
                                            int warp_m, int warp_n) {
    #pragma unroll
    for (int mt = 0; mt < 2; mt++)
        #pragma unroll
        for (int nt = 0; nt < 2; nt++)
            wmma::store_matrix_sync(&buf[(warp_m * 32 + mt * 16) * BLD + warp_n * 32 + nt * 16],
                                    acc[mt][nt], BLD, wmma::mem_row_major);
}

// CFG=0: g_h (+hH/hL imgs) = relu([mean | x] @ [W1l;W1r] + b1l)
// CFG=1: emb = [mean | h] @ [W2l;W2r] + b2l -> out (and smem); decoder+loss+final
template <int CFG>
__global__ void __launch_bounds__(512, 1)
k_gemm(const float* __restrict__ bias,
       float* __restrict__ out, int lead, int out_size) {
    extern __shared__ char sdyn[];
    int tid = threadIdx.x;
    int wid = tid >> 5;
    int warp_m = wid & 3;
    int warp_n = wid >> 2;
    int m0 = blockIdx.x * BM;

    AccFrag acc[2][2];
    #pragma unroll
    for (int mt = 0; mt < 2; mt++)
        #pragma unroll
        for (int nt = 0; nt < 2; nt++) wmma::fill_fragment(acc[mt][nt], 0.f);

    if (CFG == 0)
        gemm_pipeline(sdyn, g_meanH, g_meanL, 0, g_xH, g_xL, 1,
                      m0, acc, tid, warp_m, warp_n);
    else
        gemm_pipeline(sdyn, g_meanH, g_meanL, 2, g_hH, g_hL, 3,
                      m0, acc, tid, warp_m, warp_n);

    // ---------------- epilogue (single phase): bias (+relu / images) ------------
    float* buf = (float*)sdyn;   // 128 x BLD fp32 = 69632B, inside As+Bs region
    __nv_bfloat16* Eh = emb_ptr(sdyn, 0);
    __nv_bfloat16* El = emb_ptr(sdyn, 1);
    store_frags(buf, acc, warp_m, warp_n);
    __syncthreads();
    bool out_vec = (lead >= 0) && ((lead & 3) == 0);
    #pragma unroll
    for (int it = 0; it < 8; it++) {
        int id = tid + it * 512;
        int r = id >> 5, n = (id & 31) * 4;
        int gm = m0 + r;
        float4 v = *(float4*)&buf[r * BLD + n];
        float4 bv = *(const float4*)&bias[n];
        v.x += bv.x; v.y += bv.y; v.z += bv.z; v.w += bv.w;
        if (CFG == 0) {
            if (gm < NN) {
                v.x = fmaxf(v.x, 0.f); v.y = fmaxf(v.y, 0.f);
                v.z = fmaxf(v.z, 0.f); v.w = fmaxf(v.w, 0.f);
                size_t o = (size_t)gm * DD + n;
                *(float4*)&g_h[o] = v;
                uint2 hi, lo;
                split4(v, hi, lo);
                *(uint2*)&g_hH[o] = hi;
                *(uint2*)&g_hL[o] = lo;
            }
        } else {
            uint2 hi, lo;
            split4(v, hi, lo);
            *(uint2*)&Eh[r * BLD + n] = hi;
            *(uint2*)&El[r * BLD + n] = lo;
            if (gm < NN) {
                if (lead >= 0) {
                    size_t o = (size_t)lead + (size_t)gm * DD + n;
                    if (out_vec) {
                        *(float4*)&out[o] = v;
                    } else {
                        out[o + 0] = v.x; out[o + 1] = v.y;
                        out[o + 2] = v.z; out[o + 3] = v.w;
                    }
                } else {
                    *(float4*)&g_emb[(size_t)gm * DD + n] = v;
                }
            }
        }
    }
    __syncthreads();

    // ---------------- fused decoder (A from smem) + BCE loss + final (CFG==1) ----
    if (CFG == 1) {
        #pragma unroll
        for (int mt = 0; mt < 2; mt++)
            #pragma unroll
            for (int nt = 0; nt < 2; nt++) wmma::fill_fragment(acc[mt][nt], 0.f);

        issue_bchunk(sdyn, 0, 0, tid);
        for (int t = 0; t < 2; t++) {
            CPA_WAIT0();
            __syncthreads();
            if (t + 1 < 2) issue_bchunk(sdyn, 1, 1, tid);
            mma_dec(sdyn, t & 1, t, acc, warp_m, warp_n);
        }
        __syncthreads();

        store_frags(buf, acc, warp_m, warp_n);
        __syncthreads();
        float lp = 0.f, ln = 0.f;
        #pragma unroll
        for (int it = 0; it < 8; it++) {
            int id = tid + it * 512;
            int r = id >> 5, n = (id & 31) * 4;
            int gm = m0 + r;
            if (gm < NN) {
                float4 v = *(float4*)&buf[r * BLD + n];
                bool pos = g_yb[gm] != 0;
                float vv[4] = {v.x, v.y, v.z, v.w};
                #pragma unroll
                for (int j = 0; j < 4; j++) {
                    float t2 = pos ? -vv[j] : vv[j];
                    float sp = fmaxf(t2, 0.f) + log1pf(expf(-fabsf(t2)));
                    if (pos) lp += sp; else ln += sp;
                }
            }
        }
        #pragma unroll
        for (int o = 16; o; o >>= 1) {
            lp += __shfl_down_sync(0xffffffffu, lp, o);
            ln += __shfl_down_sync(0xffffffffu, ln, o);
        }
        if ((tid & 31) == 0) {
            atomicAdd(&g_lp, lp);
            atomicAdd(&g_ln, ln);
        }

        __syncthreads();
        if (tid == 0) {
            __threadfence();
            int old = atomicAdd(&g_done, 1);
            if (old == (int)gridDim.x - 1) {
                __threadfence();
                float lpv = *((volatile float*)&g_lp);
                float lnv = *((volatile float*)&g_ln);
                int   np  = *((volatile int*)&g_npos);
                float l2 = lpv / (fmaxf((float)np, 1.f) * (float)DD);
                float l1 = lnv / (fmaxf((float)(NN - np), 1.f) * (float)DD);
                float loss = l1 + l2;
                if (lead > 0) {
                    for (int i = 0; i < lead && i < 16; i++) out[i] = loss;
                } else if (out_size > 0) {
                    out[0] = loss;
                }
                g_lp = 0.f; g_ln = 0.f; g_npos = 0; g_done = 0;
            }
        }
    }
}

__global__ void k_copy(float* __restrict__ out, int out_size) {
    int i = blockIdx.x * blockDim.x + threadIdx.x;
    if (i < out_size && i < OUT_ELEMS) out[i] = g_emb[i];
}

// ---------------- launch ----------------
extern "C" void kernel_launch(void* const* d_in, const int* in_sizes, int n_in,
                              void* d_out, int out_size) {
    const float* x = nullptr;
    const void*  edge = nullptr;
    const void*  yv = nullptr;
    const float* Ws[5] = {nullptr, nullptr, nullptr, nullptr, nullptr};
    const float* bs[2] = {nullptr, nullptr};
    int wi = 0, bi = 0;
    for (int i = 0; i < n_in; i++) {
        int sz = in_sizes[i];
        if (sz == NN * DD && !x) x = (const float*)d_in[i];
        else if (sz == 2 * NE && !edge) edge = d_in[i];
        else if (sz == NN && !yv) yv = d_in[i];
        else if (sz == DD * DD && wi < 5) Ws[wi++] = (const float*)d_in[i];
        else if (sz == DD && bi < 2) bs[bi++] = (const float*)d_in[i];
    }
    const float* b1l = bs[0];
    const float* b2l = bs[1];
    float* out = (float*)d_out;
    int lead = out_size - OUT_ELEMS;

    cudaFuncSetAttribute(k_gemm<0>, cudaFuncAttributeMaxDynamicSharedMemorySize, SMEM_G0);
    cudaFuncSetAttribute(k_gemm<1>, cudaFuncAttributeMaxDynamicSharedMemorySize, SMEM_G1);

    k_prep <<<EDGE_BLOCKS, 256>>>(yv, edge, x, Ws[0], Ws[1], Ws[2], Ws[3], Ws[4]);
    k_scan <<<SCAN_B, 256>>>();
    k_fill <<<EDGE_BLOCKS, 256>>>(edge);

    // layer 1
    k_mean<0><<<(NN + 7) / 8, 256>>>(x);
    k_gemm<0><<<GEMM_BLOCKS, 512, SMEM_G0>>>(b1l, out, lead, out_size);

    // layer 2 + fused decoder + loss + final
    k_mean<1><<<(NN + 7) / 8, 256>>>(nullptr);
    k_gemm<1><<<GEMM_BLOCKS, 512, SMEM_G1>>>(b2l, out, lead, out_size);

    if (lead < 0) k_copy<<<(OUT_ELEMS + 255) / 256, 256>>>(out, out_size);
}

// round 16
// speedup vs baseline: 1.0468x; 1.0468x over previous
#include <cuda_runtime.h>
#include <cuda_bf16.h>
#include <mma.h>
#include <math.h>
#include <stdint.h>

using namespace nvcuda;

#define NN 50000
#define NE 800000
#define DD 128
#define OUT_ELEMS (NN * DD)
#define BM 128
#define GEMM_BLOCKS ((NN + BM - 1) / BM)
#define SCAN_B ((NN + 255) / 256)
#define EPT 4
#define EDGE_BLOCKS ((NE / EPT + 255) / 256)
#define ALD 72                                      // K=64 chunk + pad
#define BLD 136
#define AS_BYTES (2 * 2 * 128 * ALD * 2)            // 73728
#define BS_BYTES (2 * 2 * 64 * BLD * 2)             // 69632
#define EMB_BYTES (2 * 128 * BLD * 2)               // 69632
#define SMEM_G0 (AS_BYTES + BS_BYTES)               // 143360
#define SMEM_G1 (AS_BYTES + BS_BYTES + EMB_BYTES)   // 212992

// ---------------- device scratch (zero at load; every call restores zeros) --------
__device__ __align__(16) float g_mean[NN * DD];
__device__ __align__(16) float g_h[NN * DD];
__device__ __align__(16) float g_emb[NN * DD];     // only used when lead < 0
__device__ int   g_deg[NN];
__device__ int   g_off[NN + 1];
__device__ int   g_cur[NN];
__device__ int   g_col[NE];
__device__ unsigned char g_yb[NN];
__device__ float g_lp;
__device__ float g_ln;
__device__ int   g_npos;
__device__ int   g_done;
__device__ unsigned long long g_lb[SCAN_B];
__device__ __align__(16) unsigned short g_Bimg[5][2][DD * DD];

// ---------------- fp32 -> bf16 hi/lo packing ----------------
__device__ __forceinline__ void split4(float4 v, uint2& hi, uint2& lo) {
    __nv_bfloat162 h0 = __float22bfloat162_rn(make_float2(v.x, v.y));
    __nv_bfloat162 h1 = __float22bfloat162_rn(make_float2(v.z, v.w));
    float2 f0 = __bfloat1622float2(h0);
    float2 f1 = __bfloat1622float2(h1);
    __nv_bfloat162 l0 = __float22bfloat162_rn(make_float2(v.x - f0.x, v.y - f0.y));
    __nv_bfloat162 l1 = __float22bfloat162_rn(make_float2(v.z - f1.x, v.w - f1.y));
    hi = make_uint2(*(uint32_t*)&h0, *(uint32_t*)&h1);
    lo = make_uint2(*(uint32_t*)&l0, *(uint32_t*)&l1);
}

// ---------------- cp.async helpers ----------------
__device__ __forceinline__ void cpa16(uint32_t saddr, const void* g) {
    asm volatile("cp.async.cg.shared.global [%0], [%1], 16;"
                 :: "r"(saddr), "l"(g) : "memory");
}
#define CPA_COMMIT() asm volatile("cp.async.commit_group;" ::: "memory")
#define CPA_WAIT0()  asm volatile("cp.async.wait_group 0;" ::: "memory")
__device__ __forceinline__ uint32_t s_u32(const void* p) {
    return (uint32_t)__cvta_generic_to_shared(p);
}

// ---------------- per-block dtype detection ----------------
__device__ __forceinline__ int detect_e64(const void* edge) {
    __shared__ int s64;
    if (threadIdx.x == 0) s64 = 1;
    __syncthreads();
    if (threadIdx.x < 256) {
        long long v = ((const long long*)edge)[threadIdx.x];
        if (v < 0 || v >= NN) atomicAnd(&s64, 0);
    }
    __syncthreads();
    return s64;
}

__device__ __forceinline__ int edge_at(const void* edge, int idx, int e64) {
    if (e64) return (int)((const long long*)edge)[idx];
    return ((const int*)edge)[idx];
}

// ---------------- k_prep ----------------
__global__ void k_prep(const void* __restrict__ yv, const void* __restrict__ edge,
                       const float* __restrict__ W0, const float* __restrict__ W1,
                       const float* __restrict__ W2, const float* __restrict__ W3,
                       const float* __restrict__ W4) {
    __shared__ int s32;
    if (threadIdx.x == 0) s32 = 1;
    int e64 = detect_e64(edge);
    if (threadIdx.x < 64) {
        unsigned int w = ((const unsigned int*)yv)[threadIdx.x];
        if (w > 1u) atomicAnd(&s32, 0);
    }
    __syncthreads();
    int y32 = s32;

    int i = blockIdx.x * blockDim.x + threadIdx.x;
    int v = 0;
    if (i < NN) {
        if (y32) v = (((const int*)yv)[i] != 0) ? 1 : 0;
        else     v = (((const unsigned char*)yv)[i] != 0) ? 1 : 0;
        g_yb[i] = (unsigned char)v;
    }
    #pragma unroll
    for (int o = 16; o; o >>= 1) v += __shfl_down_sync(0xffffffffu, v, o);
    if ((threadIdx.x & 31) == 0 && v) atomicAdd(&g_npos, v);

    if (i < 5 * DD * DD) {
        int w = i / (DD * DD);
        int r = i % (DD * DD);
        const float* Wm = (w == 0) ? W0 : (w == 1) ? W1 : (w == 2) ? W2 : (w == 3) ? W3 : W4;
        float val = Wm[r];
        __nv_bfloat16 hi = __float2bfloat16(val);
        g_Bimg[w][0][r] = __bfloat16_as_ushort(hi);
        g_Bimg[w][1][r] = __bfloat16_as_ushort(__float2bfloat16(val - __bfloat162float(hi)));
    }

    int base = i * EPT;
    int d[EPT];
    #pragma unroll
    for (int j = 0; j < EPT; j++)
        d[j] = (base + j < NE) ? edge_at(edge, NE + base + j, e64) : -1;
    #pragma unroll
    for (int j = 0; j < EPT; j++)
        if (d[j] >= 0 && d[j] < NN) atomicAdd(&g_deg[d[j]], 1);
}

// ---------------- decoupled-lookback scan ----------------
__global__ void k_scan() {
    __shared__ int sh[256];
    __shared__ int s_ex;
    int b = blockIdx.x, t = threadIdx.x;
    int i = b * 256 + t;
    int v = (i < NN) ? g_deg[i] : 0;
    sh[t] = v;
    __syncthreads();
    for (int o = 1; o < 256; o <<= 1) {
        int add = (t >= o) ? sh[t - o] : 0;
        __syncthreads();
        sh[t] += add;
        __syncthreads();
    }
    int T = sh[255];
    if (t == 0) {
        if (b == 0) {
            atomicExch(&g_lb[0], (2ULL << 32) | (unsigned)T);
            s_ex = 0;
        } else {
            atomicExch(&g_lb[b], (1ULL << 32) | (unsigned)T);
            int ex = 0;
            for (int j = b - 1; j >= 0;) {
                unsigned long long w;
                do { w = atomicAdd(&g_lb[j], 0ULL); } while ((w >> 32) == 0ULL);
                if ((w >> 32) == 2ULL) { ex += (int)(unsigned)w; break; }
                ex += (int)(unsigned)w;
                j--;
            }
            atomicExch(&g_lb[b], (2ULL << 32) | (unsigned)(ex + T));
            s_ex = ex;
        }
    }
    __syncthreads();
    int ex = s_ex;
    if (i < NN) {
        int off = ex + sh[t] - v;
        g_off[i] = off;
        g_cur[i] = off;
        g_deg[i] = 0;
    }
    if (b == SCAN_B - 1 && t == 0) g_off[NN] = ex + T;
}

// ---------------- CSR fill ----------------
__global__ void k_fill(const void* __restrict__ edge) {
    int e64 = detect_e64(edge);
    int i = blockIdx.x * blockDim.x + threadIdx.x;
    if (i < SCAN_B) g_lb[i] = 0ULL;
    int base = i * EPT;
    int s[EPT], d[EPT];
    #pragma unroll
    for (int j = 0; j < EPT; j++) {
        if (base + j < NE) {
            d[j] = edge_at(edge, NE + base + j, e64);
            s[j] = edge_at(edge, base + j, e64);
        } else { d[j] = -1; s[j] = 0; }
    }
    #pragma unroll
    for (int j = 0; j < EPT; j++) {
        if (d[j] >= 0 && d[j] < NN && s[j] >= 0 && s[j] < NN) {
            int p = atomicAdd(&g_cur[d[j]], 1);
            g_col[p] = s[j];
        }
    }
}

// ---------------- mean aggregation: 1 warp per node ----------------
template <int SRC>
__global__ void k_mean(const float* __restrict__ feat) {
    int node = blockIdx.x * 8 + (threadIdx.x >> 5);
    int lane = threadIdx.x & 31;
    if (node >= NN) return;
    const float4* __restrict__ f = (const float4*)((SRC == 0) ? feat : (const float*)g_h);
    int s = g_off[node], e = g_off[node + 1];
    float4 acc = make_float4(0.f, 0.f, 0.f, 0.f);
    int k = s;
    for (; k + 8 <= e; k += 8) {
        int c[8];
        #pragma unroll
        for (int j = 0; j < 8; j++) c[j] = __ldg(&g_col[k + j]);
        float4 v[8];
        #pragma unroll
        for (int j = 0; j < 8; j++) v[j] = __ldg(&f[(size_t)c[j] * 32 + lane]);
        acc.x += ((v[0].x + v[1].x) + (v[2].x + v[3].x)) + ((v[4].x + v[5].x) + (v[6].x + v[7].x));
        acc.y += ((v[0].y + v[1].y) + (v[2].y + v[3].y)) + ((v[4].y + v[5].y) + (v[6].y + v[7].y));
        acc.z += ((v[0].z + v[1].z) + (v[2].z + v[3].z)) + ((v[4].z + v[5].z) + (v[6].z + v[7].z));
        acc.w += ((v[0].w + v[1].w) + (v[2].w + v[3].w)) + ((v[4].w + v[5].w) + (v[6].w + v[7].w));
    }
    for (; k < e; k++) {
        float4 v = __ldg(&f[(size_t)__ldg(&g_col[k]) * 32 + lane]);
        acc.x += v.x; acc.y += v.y; acc.z += v.z; acc.w += v.w;
    }
    float inv = 1.f / fmaxf((float)(e - s), 1.f);
    ((float4*)g_mean)[(size_t)node * 32 + lane] =
        make_float4(acc.x * inv, acc.y * inv, acc.z * inv, acc.w * inv);
}

// ---------------- double-buffered WMMA bf16x3 GEMM, K=64 chunks -------------------
// A: register prefetch + in-kernel split (R14). B: cp.async from bf16 images.
typedef wmma::fragment<wmma::accumulator, 16, 16, 16, float> AccFrag;

struct PrefA {
    float4 a[4];
};

__device__ __forceinline__ __nv_bfloat16* as_ptr(char* sdyn, int buf, int hl) {
    return (__nv_bfloat16*)sdyn + (size_t)(buf * 2 + hl) * 128 * ALD;
}
__device__ __forceinline__ __nv_bfloat16* bs_ptr(char* sdyn, int buf, int hl) {
    return (__nv_bfloat16*)(sdyn + AS_BYTES) + (size_t)(buf * 2 + hl) * 64 * BLD;
}
__device__ __forceinline__ __nv_bfloat16* emb_ptr(char* sdyn, int hl) {
    return (__nv_bfloat16*)(sdyn + AS_BYTES + BS_BYTES) + (size_t)hl * 128 * BLD;
}

__device__ __forceinline__ void pf_loadA(PrefA& p, const float* __restrict__ Asrc,
                                         int c, int m0, int tid) {
    #pragma unroll
    for (int it = 0; it < 4; it++) {
        int id = tid + it * 512;
        int row = id >> 4, q = id & 15;
        int gm = m0 + row;
        p.a[it] = (gm < NN) ? *(const float4*)&Asrc[(size_t)gm * DD + c * 64 + q * 4]
                            : make_float4(0.f, 0.f, 0.f, 0.f);
    }
}

__device__ __forceinline__ void pf_storeA(const PrefA& p, char* sdyn, int buf, int tid) {
    __nv_bfloat16* Ah = as_ptr(sdyn, buf, 0);
    __nv_bfloat16* Al = as_ptr(sdyn, buf, 1);
    #pragma unroll
    for (int it = 0; it < 4; it++) {
        int id = tid + it * 512;
        int row = id >> 4, q = id & 15;
        uint2 hi, lo;
        split4(p.a[it], hi, lo);
        *(uint2*)&Ah[row * ALD + q * 4] = hi;
        *(uint2*)&Al[row * ALD + q * 4] = lo;
    }
}

// issue B chunk via cp.async: 2 images x 2 halves = 4 x 16B per thread
__device__ __forceinline__ void issue_b(char* sdyn, int buf, int wsel, int c, int tid) {
    #pragma unroll
    for (int hl = 0; hl < 2; hl++) {
        __nv_bfloat16* B = bs_ptr(sdyn, buf, hl);
        #pragma unroll
        for (int half = 0; half < 2; half++) {
            int id = tid + half * 512;
            int k = id >> 4, p = id & 15;
            cpa16(s_u32(B) + (uint32_t)(k * BLD + p * 8) * 2,
                  &g_Bimg[wsel][hl][(c * 64 + k) * DD + p * 8]);
        }
    }
    CPA_COMMIT();
}

__device__ __forceinline__ void mma_chunk(char* sdyn, int buf,
                                          AccFrag (&acc)[2][2], int warp_m, int warp_n) {
    __nv_bfloat16* Ah = as_ptr(sdyn, buf, 0);
    __nv_bfloat16* Al = as_ptr(sdyn, buf, 1);
    __nv_bfloat16* Bh = bs_ptr(sdyn, buf, 0);
    __nv_bfloat16* Bl = bs_ptr(sdyn, buf, 1);
    #pragma unroll
    for (int ks = 0; ks < 4; ks++) {
        wmma::fragment<wmma::matrix_a, 16, 16, 16, __nv_bfloat16, wmma::row_major> a_hi[2], a_lo[2];
        #pragma unroll
        for (int mt = 0; mt < 2; mt++) {
            int mr = (warp_m * 32 + mt * 16) * ALD + ks * 16;
            wmma::load_matrix_sync(a_hi[mt], &Ah[mr], ALD);
            wmma::load_matrix_sync(a_lo[mt], &Al[mr], ALD);
        }
        #pragma unroll
        for (int nt = 0; nt < 2; nt++) {
            int nb = warp_n * 32 + nt * 16;
            wmma::fragment<wmma::matrix_b, 16, 16, 16, __nv_bfloat16, wmma::row_major> b_hi, b_lo;
            wmma::load_matrix_sync(b_hi, &Bh[ks * 16 * BLD + nb], BLD);
            wmma::load_matrix_sync(b_lo, &Bl[ks * 16 * BLD + nb], BLD);
            #pragma unroll
            for (int mt = 0; mt < 2; mt++) {
                wmma::mma_sync(acc[mt][nt], a_hi[mt], b_hi, acc[mt][nt]);
                wmma::mma_sync(acc[mt][nt], a_hi[mt], b_lo, acc[mt][nt]);
                wmma::mma_sync(acc[mt][nt], a_lo[mt], b_hi, acc[mt][nt]);
            }
        }
    }
}

// decoder mma: A frags from smem emb image (BLD leading dim), K=64 chunk c
__device__ __forceinline__ void mma_dec(char* sdyn, int buf, int c,
                                        AccFrag (&acc)[2][2], int warp_m, int warp_n) {
    __nv_bfloat16* Eh = emb_ptr(sdyn, 0);
    __nv_bfloat16* El = emb_ptr(sdyn, 1);
    __nv_bfloat16* Bh = bs_ptr(sdyn, buf, 0);
    __nv_bfloat16* Bl = bs_ptr(sdyn, buf, 1);
    #pragma unroll
    for (int ks = 0; ks < 4; ks++) {
        wmma::fragment<wmma::matrix_a, 16, 16, 16, __nv_bfloat16, wmma::row_major> a_hi[2], a_lo[2];
        #pragma unroll
        for (int mt = 0; mt < 2; mt++) {
            int mr = (warp_m * 32 + mt * 16) * BLD + c * 64 + ks * 16;
            wmma::load_matrix_sync(a_hi[mt], &Eh[mr], BLD);
            wmma::load_matrix_sync(a_lo[mt], &El[mr], BLD);
        }
        #pragma unroll
        for (int nt = 0; nt < 2; nt++) {
            int nb = warp_n * 32 + nt * 16;
            wmma::fragment<wmma::matrix_b, 16, 16, 16, __nv_bfloat16, wmma::row_major> b_hi, b_lo;
            wmma::load_matrix_sync(b_hi, &Bh[ks * 16 * BLD + nb], BLD);
            wmma::load_matrix_sync(b_lo, &Bl[ks * 16 * BLD + nb], BLD);
            #pragma unroll
            for (int mt = 0; mt < 2; mt++) {
                wmma::mma_sync(acc[mt][nt], a_hi[mt], b_hi, acc[mt][nt]);
                wmma::mma_sync(acc[mt][nt], a_hi[mt], b_lo, acc[mt][nt]);
                wmma::mma_sync(acc[mt][nt], a_lo[mt], b_hi, acc[mt][nt]);
            }
        }
    }
}

// pipelined accumulation over 2 sources x 2 K-chunks = 4 iterations
__device__ __forceinline__ void gemm_pipeline(
    char* sdyn,
    const float* __restrict__ src0, int wsel0,
    const float* __restrict__ src1, int wsel1,
    int m0, AccFrag (&acc)[2][2], int tid, int warp_m, int warp_n) {
    PrefA p;
    pf_loadA(p, src0, 0, m0, tid);
    issue_b(sdyn, 0, wsel0, 0, tid);
    const int T = 4;
    for (int t = 0; t < T; t++) {
        int buf = t & 1;
        pf_storeA(p, sdyn, buf, tid);
        CPA_WAIT0();                 // B chunk t landed
        __syncthreads();             // A stores + B visible; mma(t-1) done (WAR safe)
        if (t + 1 < T) {
            int nsrc = (t + 1) >> 1;
            pf_loadA(p, nsrc ? src1 : src0, (t + 1) & 1, m0, tid);
            issue_b(sdyn, (t + 1) & 1, nsrc ? wsel1 : wsel0, (t + 1) & 1, tid);
        }
        mma_chunk(sdyn, buf, acc, warp_m, warp_n);
    }
    __syncthreads();
}

// store all 16 warps' acc frags into one 128 x BLD fp32 smem tile
__device__ __forceinline__ void store_frags(float* buf, AccFrag (&acc)[2][2],
                                            int warp_m, int warp_n) {
    #pragma unroll
    for (int mt = 0; mt < 2; mt++)
        #pragma unroll
        for (int nt = 0; nt < 2; nt++)
            wmma::store_matrix_sync(&buf[(warp_m * 32 + mt * 16) * BLD + warp_n * 32 + nt * 16],
                                    acc[mt][nt], BLD, wmma::mem_row_major);
}

// CFG=0: g_h = relu([g_mean | x] @ [W1l;W1r] + b1l)
// CFG=1: emb = [g_mean | g_h] @ [W2l;W2r] + b2l -> out (and smem); decoder+loss+final
template <int CFG>
__global__ void __launch_bounds__(512, 1)
k_gemm(const float* __restrict__ xparam, const float* __restrict__ bias,
       float* __restrict__ out, int lead, int out_size) {
    extern __shared__ char sdyn[];
    int tid = threadIdx.x;
    int wid = tid >> 5;
    int warp_m = wid & 3;
    int warp_n = wid >> 2;
    int m0 = blockIdx.x * BM;

    AccFrag acc[2][2];
    #pragma unroll
    for (int mt = 0; mt < 2; mt++)
        #pragma unroll
        for (int nt = 0; nt < 2; nt++) wmma::fill_fragment(acc[mt][nt], 0.f);

    if (CFG == 0)
        gemm_pipeline(sdyn, g_mean, 0, xparam, 1, m0, acc, tid, warp_m, warp_n);
    else
        gemm_pipeline(sdyn, g_mean, 2, g_h, 3, m0, acc, tid, warp_m, warp_n);

    // ---------------- epilogue (single phase): bias (+relu / emb image) ---------
    float* buf = (float*)sdyn;   // 128 x BLD fp32 = 69632B, inside As+Bs region
    __nv_bfloat16* Eh = emb_ptr(sdyn, 0);
    __nv_bfloat16* El = emb_ptr(sdyn, 1);
    store_frags(buf, acc, warp_m, warp_n);
    __syncthreads();
    bool out_vec = (lead >= 0) && ((lead & 3) == 0);
    #pragma unroll
    for (int it = 0; it < 8; it++) {
        int id = tid + it * 512;
        int r = id >> 5, n = (id & 31) * 4;
        int gm = m0 + r;
        float4 v = *(float4*)&buf[r * BLD + n];
        float4 bv = *(const float4*)&bias[n];
        v.x += bv.x; v.y += bv.y; v.z += bv.z; v.w += bv.w;
        if (CFG == 0) {
            if (gm < NN) {
                v.x = fmaxf(v.x, 0.f); v.y = fmaxf(v.y, 0.f);
                v.z = fmaxf(v.z, 0.f); v.w = fmaxf(v.w, 0.f);
                *(float4*)&g_h[(size_t)gm * DD + n] = v;
            }
        } else {
            uint2 hi, lo;
            split4(v, hi, lo);
            *(uint2*)&Eh[r * BLD + n] = hi;
            *(uint2*)&El[r * BLD + n] = lo;
            if (gm < NN) {
                if (lead >= 0) {
                    size_t o = (size_t)lead + (size_t)gm * DD + n;
                    if (out_vec) {
                        *(float4*)&out[o] = v;
                    } else {
                        out[o + 0] = v.x; out[o + 1] = v.y;
                        out[o + 2] = v.z; out[o + 3] = v.w;
                    }
                } else {
                    *(float4*)&g_emb[(size_t)gm * DD + n] = v;
                }
            }
        }
    }
    __syncthreads();

    // ---------------- fused decoder (A from smem) + BCE loss + final (CFG==1) ----
    if (CFG == 1) {
        #pragma unroll
        for (int mt = 0; mt < 2; mt++)
            #pragma unroll
            for (int nt = 0; nt < 2; nt++) wmma::fill_fragment(acc[mt][nt], 0.f);

        issue_b(sdyn, 0, 4, 0, tid);
        for (int t = 0; t < 2; t++) {
            CPA_WAIT0();
            __syncthreads();
            if (t + 1 < 2) issue_b(sdyn, 1, 4, 1, tid);
            mma_dec(sdyn, t & 1, t, acc, warp_m, warp_n);
        }
        __syncthreads();

        store_frags(buf, acc, warp_m, warp_n);
        __syncthreads();
        float lp = 0.f, ln = 0.f;
        #pragma unroll
        for (int it = 0; it < 8; it++) {
            int id = tid + it * 512;
            int r = id >> 5, n = (id & 31) * 4;
            int gm = m0 + r;
            if (gm < NN) {
                float4 v = *(float4*)&buf[r * BLD + n];
                bool pos = g_yb[gm] != 0;
                float vv[4] = {v.x, v.y, v.z, v.w};
                #pragma unroll
                for (int j = 0; j < 4; j++) {
                    float t2 = pos ? -vv[j] : vv[j];
                    float sp = fmaxf(t2, 0.f) + log1pf(expf(-fabsf(t2)));
                    if (pos) lp += sp; else ln += sp;
                }
            }
        }
        #pragma unroll
        for (int o = 16; o; o >>= 1) {
            lp += __shfl_down_sync(0xffffffffu, lp, o);
            ln += __shfl_down_sync(0xffffffffu, ln, o);
        }
        if ((tid & 31) == 0) {
            atomicAdd(&g_lp, lp);
            atomicAdd(&g_ln, ln);
        }

        __syncthreads();
        if (tid == 0) {
            __threadfence();
            int old = atomicAdd(&g_done, 1);
            if (old == (int)gridDim.x - 1) {
                __threadfence();
                float lpv = *((volatile float*)&g_lp);
                float lnv = *((volatile float*)&g_ln);
                int   np  = *((volatile int*)&g_npos);
                float l2 = lpv / (fmaxf((float)np, 1.f) * (float)DD);
                float l1 = lnv / (fmaxf((float)(NN - np), 1.f) * (float)DD);
                float loss = l1 + l2;
                if (lead > 0) {
                    for (int i = 0; i < lead && i < 16; i++) out[i] = loss;
                } else if (out_size > 0) {
                    out[0] = loss;
                }
                g_lp = 0.f; g_ln = 0.f; g_npos = 0; g_done = 0;
            }
        }
    }
}

__global__ void k_copy(float* __restrict__ out, int out_size) {
    int i = blockIdx.x * blockDim.x + threadIdx.x;
    if (i < out_size && i < OUT_ELEMS) out[i] = g_emb[i];
}

// ---------------- launch ----------------
extern "C" void kernel_launch(void* const* d_in, const int* in_sizes, int n_in,
                              void* d_out, int out_size) {
    const float* x = nullptr;
    const void*  edge = nullptr;
    const void*  yv = nullptr;
    const float* Ws[5] = {nullptr, nullptr, nullptr, nullptr, nullptr};
    const float* bs[2] = {nullptr, nullptr};
    int wi = 0, bi = 0;
    for (int i = 0; i < n_in; i++) {
        int sz = in_sizes[i];
        if (sz == NN * DD && !x) x = (const float*)d_in[i];
        else if (sz == 2 * NE && !edge) edge = d_in[i];
        else if (sz == NN && !yv) yv = d_in[i];
        else if (sz == DD * DD && wi < 5) Ws[wi++] = (const float*)d_in[i];
        else if (sz == DD && bi < 2) bs[bi++] = (const float*)d_in[i];
    }
    const float* b1l = bs[0];
    const float* b2l = bs[1];
    float* out = (float*)d_out;
    int lead = out_size - OUT_ELEMS;

    cudaFuncSetAttribute(k_gemm<0>, cudaFuncAttributeMaxDynamicSharedMemorySize, SMEM_G0);
    cudaFuncSetAttribute(k_gemm<1>, cudaFuncAttributeMaxDynamicSharedMemorySize, SMEM_G1);

    k_prep <<<EDGE_BLOCKS, 256>>>(yv, edge, Ws[0], Ws[1], Ws[2], Ws[3], Ws[4]);
    k_scan <<<SCAN_B, 256>>>();
    k_fill <<<EDGE_BLOCKS, 256>>>(edge);

    // layer 1
    k_mean<0><<<(NN + 7) / 8, 256>>>(x);
    k_gemm<0><<<GEMM_BLOCKS, 512, SMEM_G0>>>(x, b1l, out, lead, out_size);

    // layer 2 + fused decoder + loss + final
    k_mean<1><<<(NN + 7) / 8, 256>>>(nullptr);
    k_gemm<1><<<GEMM_BLOCKS, 512, SMEM_G1>>>(nullptr, b2l, out, lead, out_size);

    if (lead < 0) k_copy<<<(OUT_ELEMS + 255) / 256, 256>>>(out, out_size);
}

// round 17
// speedup vs baseline: 1.0602x; 1.0128x over previous
#include <cuda_runtime.h>
#include <cuda_bf16.h>
#include <mma.h>
#include <math.h>
#include <stdint.h>

using namespace nvcuda;

#define NN 50000
#define NE 800000
#define DD 128
#define OUT_ELEMS (NN * DD)
#define BM 128
#define GEMM_BLOCKS ((NN + BM - 1) / BM)
#define SCAN_B ((NN + 255) / 256)
#define EPT 4
#define EDGE_BLOCKS ((NE / EPT + 255) / 256)
#define ALD 72
#define BLD 136
#define AS_BYTES (2 * 2 * 128 * ALD * 2)            // 73728
#define BS_BYTES (2 * 2 * 64 * BLD * 2)             // 69632
#define EMB_BYTES (2 * 128 * BLD * 2)               // 69632
#define SMEM_G0 (AS_BYTES + BS_BYTES)               // 143360
#define SMEM_G1 (AS_BYTES + BS_BYTES + EMB_BYTES)   // 212992

// ---------------- device scratch (zero at load; every call restores zeros) --------
__device__ __align__(16) float g_mean[NN * DD];
__device__ __align__(16) float g_h[NN * DD];
__device__ __align__(16) float g_emb[NN * DD];
__device__ int   g_deg[NN];
__device__ int   g_off[NN + 1];
__device__ int   g_cur[NN];
__device__ int   g_col[NE];
__device__ unsigned char g_yb[NN];
__device__ float g_lp;
__device__ float g_ln;
__device__ int   g_npos;
__device__ int   g_done;
__device__ unsigned long long g_lb[SCAN_B];
__device__ __align__(16) unsigned short g_Bimg[5][2][DD * DD];

// ---------------- fp32 -> bf16 hi/lo packing ----------------
__device__ __forceinline__ void split4(float4 v, uint2& hi, uint2& lo) {
    __nv_bfloat162 h0 = __float22bfloat162_rn(make_float2(v.x, v.y));
    __nv_bfloat162 h1 = __float22bfloat162_rn(make_float2(v.z, v.w));
    float2 f0 = __bfloat1622float2(h0);
    float2 f1 = __bfloat1622float2(h1);
    __nv_bfloat162 l0 = __float22bfloat162_rn(make_float2(v.x - f0.x, v.y - f0.y));
    __nv_bfloat162 l1 = __float22bfloat162_rn(make_float2(v.z - f1.x, v.w - f1.y));
    hi = make_uint2(*(uint32_t*)&h0, *(uint32_t*)&h1);
    lo = make_uint2(*(uint32_t*)&l0, *(uint32_t*)&l1);
}

// ---------------- per-block dtype detection ----------------
__device__ __forceinline__ int detect_e64(const void* edge) {
    __shared__ int s64;
    if (threadIdx.x == 0) s64 = 1;
    __syncthreads();
    if (threadIdx.x < 256) {
        long long v = ((const long long*)edge)[threadIdx.x];
        if (v < 0 || v >= NN) atomicAnd(&s64, 0);
    }
    __syncthreads();
    return s64;
}

// load 4 consecutive edge indices starting at idx (idx % 4 == 0) into o[0..3]
__device__ __forceinline__ void edge_at4(const void* edge, int idx, int e64, int* o) {
    if (e64) {
        longlong2 p0 = ((const longlong2*)edge)[idx >> 1];
        longlong2 p1 = ((const longlong2*)edge)[(idx >> 1) + 1];
        o[0] = (int)p0.x; o[1] = (int)p0.y; o[2] = (int)p1.x; o[3] = (int)p1.y;
    } else {
        int4 p = ((const int4*)edge)[idx >> 2];
        o[0] = p.x; o[1] = p.y; o[2] = p.z; o[3] = p.w;
    }
}

// ---------------- k_prep ----------------
__global__ void k_prep(const void* __restrict__ yv, const void* __restrict__ edge,
                       const float* __restrict__ W0, const float* __restrict__ W1,
                       const float* __restrict__ W2, const float* __restrict__ W3,
                       const float* __restrict__ W4) {
    __shared__ int s32;
    if (threadIdx.x == 0) s32 = 1;
    int e64 = detect_e64(edge);
    if (threadIdx.x < 64) {
        unsigned int w = ((const unsigned int*)yv)[threadIdx.x];
        if (w > 1u) atomicAnd(&s32, 0);
    }
    __syncthreads();
    int y32 = s32;

    int i = blockIdx.x * blockDim.x + threadIdx.x;
    int v = 0;
    if (i < NN) {
        if (y32) v = (((const int*)yv)[i] != 0) ? 1 : 0;
        else     v = (((const unsigned char*)yv)[i] != 0) ? 1 : 0;
        g_yb[i] = (unsigned char)v;
    }
    #pragma unroll
    for (int o = 16; o; o >>= 1) v += __shfl_down_sync(0xffffffffu, v, o);
    if ((threadIdx.x & 31) == 0 && v) atomicAdd(&g_npos, v);

    if (i < 5 * DD * DD) {
        int w = i / (DD * DD);
        int r = i % (DD * DD);
        const float* Wm = (w == 0) ? W0 : (w == 1) ? W1 : (w == 2) ? W2 : (w == 3) ? W3 : W4;
        float val = Wm[r];
        __nv_bfloat16 hi = __float2bfloat16(val);
        g_Bimg[w][0][r] = __bfloat16_as_ushort(hi);
        g_Bimg[w][1][r] = __bfloat16_as_ushort(__float2bfloat16(val - __bfloat162float(hi)));
    }

    int base = i * EPT;
    if (base < NE) {
        int d[EPT];
        edge_at4(edge, NE + base, e64, d);     // NE + base % 4 == 0
        #pragma unroll
        for (int j = 0; j < EPT; j++)
            if (base + j < NE && d[j] >= 0 && d[j] < NN) atomicAdd(&g_deg[d[j]], 1);
    }
}

// ---------------- decoupled-lookback scan ----------------
__global__ void k_scan() {
    __shared__ int sh[256];
    __shared__ int s_ex;
    int b = blockIdx.x, t = threadIdx.x;
    int i = b * 256 + t;
    int v = (i < NN) ? g_deg[i] : 0;
    sh[t] = v;
    __syncthreads();
    for (int o = 1; o < 256; o <<= 1) {
        int add = (t >= o) ? sh[t - o] : 0;
        __syncthreads();
        sh[t] += add;
        __syncthreads();
    }
    int T = sh[255];
    if (t == 0) {
        if (b == 0) {
            atomicExch(&g_lb[0], (2ULL << 32) | (unsigned)T);
            s_ex = 0;
        } else {
            atomicExch(&g_lb[b], (1ULL << 32) | (unsigned)T);
            int ex = 0;
            for (int j = b - 1; j >= 0;) {
                unsigned long long w;
                do { w = atomicAdd(&g_lb[j], 0ULL); } while ((w >> 32) == 0ULL);
                if ((w >> 32) == 2ULL) { ex += (int)(unsigned)w; break; }
                ex += (int)(unsigned)w;
                j--;
            }
            atomicExch(&g_lb[b], (2ULL << 32) | (unsigned)(ex + T));
            s_ex = ex;
        }
    }
    __syncthreads();
    int ex = s_ex;
    if (i < NN) {
        int off = ex + sh[t] - v;
        g_off[i] = off;
        g_cur[i] = off;
        g_deg[i] = 0;
    }
    if (b == SCAN_B - 1 && t == 0) g_off[NN] = ex + T;
}

// ---------------- CSR fill ----------------
__global__ void k_fill(const void* __restrict__ edge) {
    int e64 = detect_e64(edge);
    int i = blockIdx.x * blockDim.x + threadIdx.x;
    if (i < SCAN_B) g_lb[i] = 0ULL;
    int base = i * EPT;
    if (base >= NE) return;
    int s[EPT], d[EPT];
    edge_at4(edge, base, e64, s);
    edge_at4(edge, NE + base, e64, d);
    #pragma unroll
    for (int j = 0; j < EPT; j++) {
        if (base + j < NE && d[j] >= 0 && d[j] < NN && s[j] >= 0 && s[j] < NN) {
            int p = atomicAdd(&g_cur[d[j]], 1);
            g_col[p] = s[j];
        }
    }
}

// ---------------- mean aggregation: 1 warp per node ----------------
template <int SRC>
__global__ void k_mean(const float* __restrict__ feat) {
    int node = blockIdx.x * 8 + (threadIdx.x >> 5);
    int lane = threadIdx.x & 31;
    if (node >= NN) return;
    const float4* __restrict__ f = (const float4*)((SRC == 0) ? feat : (const float*)g_h);
    int s = g_off[node], e = g_off[node + 1];
    float4 acc = make_float4(0.f, 0.f, 0.f, 0.f);
    int k = s;
    for (; k + 8 <= e; k += 8) {
        int c[8];
        #pragma unroll
        for (int j = 0; j < 8; j++) c[j] = __ldg(&g_col[k + j]);
        float4 v[8];
        #pragma unroll
        for (int j = 0; j < 8; j++) v[j] = __ldg(&f[(size_t)c[j] * 32 + lane]);
        acc.x += ((v[0].x + v[1].x) + (v[2].x + v[3].x)) + ((v[4].x + v[5].x) + (v[6].x + v[7].x));
        acc.y += ((v[0].y + v[1].y) + (v[2].y + v[3].y)) + ((v[4].y + v[5].y) + (v[6].y + v[7].y));
        acc.z += ((v[0].z + v[1].z) + (v[2].z + v[3].z)) + ((v[4].z + v[5].z) + (v[6].z + v[7].z));
        acc.w += ((v[0].w + v[1].w) + (v[2].w + v[3].w)) + ((v[4].w + v[5].w) + (v[6].w + v[7].w));
    }
    for (; k < e; k++) {
        float4 v = __ldg(&f[(size_t)__ldg(&g_col[k]) * 32 + lane]);
        acc.x += v.x; acc.y += v.y; acc.z += v.z; acc.w += v.w;
    }
    float inv = 1.f / fmaxf((float)(e - s), 1.f);
    ((float4*)g_mean)[(size_t)node * 32 + lane] =
        make_float4(acc.x * inv, acc.y * inv, acc.z * inv, acc.w * inv);
}

// ---------------- double-buffered WMMA bf16x3 GEMM, K=64 chunks (R14) -------------
typedef wmma::fragment<wmma::accumulator, 16, 16, 16, float> AccFrag;

struct Pref {
    float4 a[4];
    uint4  b[4];
};

__device__ __forceinline__ __nv_bfloat16* as_ptr(char* sdyn, int buf, int hl) {
    return (__nv_bfloat16*)sdyn + (size_t)(buf * 2 + hl) * 128 * ALD;
}
__device__ __forceinline__ __nv_bfloat16* bs_ptr(char* sdyn, int buf, int hl) {
    return (__nv_bfloat16*)(sdyn + AS_BYTES) + (size_t)(buf * 2 + hl) * 64 * BLD;
}
__device__ __forceinline__ __nv_bfloat16* emb_ptr(char* sdyn, int hl) {
    return (__nv_bfloat16*)(sdyn + AS_BYTES + BS_BYTES) + (size_t)hl * 128 * BLD;
}

__device__ __forceinline__ void pf_load(Pref& p, const float* __restrict__ Asrc,
                                        int wsel, int c, int m0, int tid) {
    #pragma unroll
    for (int it = 0; it < 4; it++) {
        int id = tid + it * 512;
        int row = id >> 4, q = id & 15;
        int gm = m0 + row;
        p.a[it] = (gm < NN) ? *(const float4*)&Asrc[(size_t)gm * DD + c * 64 + q * 4]
                            : make_float4(0.f, 0.f, 0.f, 0.f);
    }
    #pragma unroll
    for (int hl = 0; hl < 2; hl++)
        #pragma unroll
        for (int half = 0; half < 2; half++) {
            int id = tid + half * 512;
            int k = id >> 4, c16 = id & 15;
            p.b[hl * 2 + half] =
                ((const uint4*)&g_Bimg[wsel][hl][(c * 64 + k) * DD])[c16];
        }
}

__device__ __forceinline__ void pf_store(const Pref& p, char* sdyn, int buf, int tid) {
    __nv_bfloat16* Ah = as_ptr(sdyn, buf, 0);
    __nv_bfloat16* Al = as_ptr(sdyn, buf, 1);
    #pragma unroll
    for (int it = 0; it < 4; it++) {
        int id = tid + it * 512;
        int row = id >> 4, q = id & 15;
        uint2 hi, lo;
        split4(p.a[it], hi, lo);
        *(uint2*)&Ah[row * ALD + q * 4] = hi;
        *(uint2*)&Al[row * ALD + q * 4] = lo;
    }
    #pragma unroll
    for (int hl = 0; hl < 2; hl++) {
        __nv_bfloat16* B = bs_ptr(sdyn, buf, hl);
        #pragma unroll
        for (int half = 0; half < 2; half++) {
            int id = tid + half * 512;
            int k = id >> 4, c16 = id & 15;
            ((uint4*)&B[k * BLD])[c16] = p.b[hl * 2 + half];
        }
    }
}

__device__ __forceinline__ void mma_chunk(char* sdyn, int buf,
                                          AccFrag (&acc)[2][2], int warp_m, int warp_n) {
    __nv_bfloat16* Ah = as_ptr(sdyn, buf, 0);
    __nv_bfloat16* Al = as_ptr(sdyn, buf, 1);
    __nv_bfloat16* Bh = bs_ptr(sdyn, buf, 0);
    __nv_bfloat16* Bl = bs_ptr(sdyn, buf, 1);
    #pragma unroll
    for (int ks = 0; ks < 4; ks++) {
        wmma::fragment<wmma::matrix_a, 16, 16, 16, __nv_bfloat16, wmma::row_major> a_hi[2], a_lo[2];
        #pragma unroll
        for (int mt = 0; mt < 2; mt++) {
            int mr = (warp_m * 32 + mt * 16) * ALD + ks * 16;
            wmma::load_matrix_sync(a_hi[mt], &Ah[mr], ALD);
            wmma::load_matrix_sync(a_lo[mt], &Al[mr], ALD);
        }
        #pragma unroll
        for (int nt = 0; nt < 2; nt++) {
            int nb = warp_n * 32 + nt * 16;
            wmma::fragment<wmma::matrix_b, 16, 16, 16, __nv_bfloat16, wmma::row_major> b_hi, b_lo;
            wmma::load_matrix_sync(b_hi, &Bh[ks * 16 * BLD + nb], BLD);
            wmma::load_matrix_sync(b_lo, &Bl[ks * 16 * BLD + nb], BLD);
            #pragma unroll
            for (int mt = 0; mt < 2; mt++) {
                wmma::mma_sync(acc[mt][nt], a_hi[mt], b_hi, acc[mt][nt]);
                wmma::mma_sync(acc[mt][nt], a_hi[mt], b_lo, acc[mt][nt]);
                wmma::mma_sync(acc[mt][nt], a_lo[mt], b_hi, acc[mt][nt]);
            }
        }
    }
}

// decoder mma: A frags from smem emb image (BLD leading dim), K=64 chunk c
__device__ __forceinline__ void mma_dec(char* sdyn, int buf, int c,
                                        AccFrag (&acc)[2][2], int warp_m, int warp_n) {
    __nv_bfloat16* Eh = emb_ptr(sdyn, 0);
    __nv_bfloat16* El = emb_ptr(sdyn, 1);
    __nv_bfloat16* Bh = bs_ptr(sdyn, buf, 0);
    __nv_bfloat16* Bl = bs_ptr(sdyn, buf, 1);
    #pragma unroll
    for (int ks = 0; ks < 4; ks++) {
        wmma::fragment<wmma::matrix_a, 16, 16, 16, __nv_bfloat16, wmma::row_major> a_hi[2], a_lo[2];
        #pragma unroll
        for (int mt = 0; mt < 2; mt++) {
            int mr = (warp_m * 32 + mt * 16) * BLD + c * 64 + ks * 16;
            wmma::load_matrix_sync(a_hi[mt], &Eh[mr], BLD);
            wmma::load_matrix_sync(a_lo[mt], &El[mr], BLD);
        }
        #pragma unroll
        for (int nt = 0; nt < 2; nt++) {
            int nb = warp_n * 32 + nt * 16;
            wmma::fragment<wmma::matrix_b, 16, 16, 16, __nv_bfloat16, wmma::row_major> b_hi, b_lo;
            wmma::load_matrix_sync(b_hi, &Bh[ks * 16 * BLD + nb], BLD);
            wmma::load_matrix_sync(b_lo, &Bl[ks * 16 * BLD + nb], BLD);
            #pragma unroll
            for (int mt = 0; mt < 2; mt++) {
                wmma::mma_sync(acc[mt][nt], a_hi[mt], b_hi, acc[mt][nt]);
                wmma::mma_sync(acc[mt][nt], a_hi[mt], b_lo, acc[mt][nt]);
                wmma::mma_sync(acc[mt][nt], a_lo[mt], b_hi, acc[mt][nt]);
            }
        }
    }
}

__device__ __forceinline__ void gemm_pipeline(
    char* sdyn,
    const float* __restrict__ src0, int wsel0,
    const float* __restrict__ src1, int wsel1,
    int m0, AccFrag (&acc)[2][2], int tid, int warp_m, int warp_n) {
    Pref p;
    pf_load(p, src0, wsel0, 0, m0, tid);
    const int T = 4;
    for (int t = 0; t < T; t++) {
        int buf = t & 1;
        pf_store(p, sdyn, buf, tid);
        __syncthreads();
        if (t + 1 < T) {
            const float* nptr = ((t + 1) >> 1) ? src1 : src0;
            int nwsel = ((t + 1) >> 1) ? wsel1 : wsel0;
            pf_load(p, nptr, nwsel, (t + 1) & 1, m0, tid);
        }
        mma_chunk(sdyn, buf, acc, warp_m, warp_n);
    }
    __syncthreads();
}

__device__ __forceinline__ void store_frags(float* buf, AccFrag (&acc)[2][2],
                                            int warp_m, int warp_n) {
    #pragma unroll
    for (int mt = 0; mt < 2; mt++)
        #pragma unroll
        for (int nt = 0; nt < 2; nt++)
            wmma::store_matrix_sync(&buf[(warp_m * 32 + mt * 16) * BLD + warp_n * 32 + nt * 16],
                                    acc[mt][nt], BLD, wmma::mem_row_major);
}

// CFG=0: g_h = relu([g_mean | x] @ [W1l;W1r] + b1l)
// CFG=1: emb = [g_mean | g_h] @ [W2l;W2r] + b2l -> out (and smem); decoder+loss+final
template <int CFG>
__global__ void __launch_bounds__(512, 1)
k_gemm(const float* __restrict__ xparam, const float* __restrict__ bias,
       float* __restrict__ out, int lead, int out_size) {
    extern __shared__ char sdyn[];
    int tid = threadIdx.x;
    int wid = tid >> 5;
    int warp_m = wid & 3;
    int warp_n = wid >> 2;
    int m0 = blockIdx.x * BM;

    AccFrag acc[2][2];
    #pragma unroll
    for (int mt = 0; mt < 2; mt++)
        #pragma unroll
        for (int nt = 0; nt < 2; nt++) wmma::fill_fragment(acc[mt][nt], 0.f);

    if (CFG == 0)
        gemm_pipeline(sdyn, g_mean, 0, xparam, 1, m0, acc, tid, warp_m, warp_n);
    else
        gemm_pipeline(sdyn, g_mean, 2, g_h, 3, m0, acc, tid, warp_m, warp_n);

    // CFG1: prestage BOTH decoder B chunks into registers now (Bs free after loop)
    uint4 pb[8];
    if (CFG == 1) {
        #pragma unroll
        for (int c = 0; c < 2; c++)
            #pragma unroll
            for (int hl = 0; hl < 2; hl++)
                #pragma unroll
                for (int half = 0; half < 2; half++) {
                    int id = tid + half * 512;
                    int k = id >> 4, c16 = id & 15;
                    pb[c * 4 + hl * 2 + half] =
                        ((const uint4*)&g_Bimg[4][hl][(c * 64 + k) * DD])[c16];
                }
    }

    // ---------------- epilogue (single phase): bias (+relu / emb image) ---------
    float* buf = (float*)sdyn;   // 128 x BLD fp32 in As region (Bs region untouched)
    __nv_bfloat16* Eh = emb_ptr(sdyn, 0);
    __nv_bfloat16* El = emb_ptr(sdyn, 1);
    store_frags(buf, acc, warp_m, warp_n);
    __syncthreads();
    bool out_vec = (lead >= 0) && ((lead & 3) == 0);
    #pragma unroll
    for (int it = 0; it < 8; it++) {
        int id = tid + it * 512;
        int r = id >> 5, n = (id & 31) * 4;
        int gm = m0 + r;
        float4 v = *(float4*)&buf[r * BLD + n];
        float4 bv = *(const float4*)&bias[n];
        v.x += bv.x; v.y += bv.y; v.z += bv.z; v.w += bv.w;
        if (CFG == 0) {
            if (gm < NN) {
                v.x = fmaxf(v.x, 0.f); v.y = fmaxf(v.y, 0.f);
                v.z = fmaxf(v.z, 0.f); v.w = fmaxf(v.w, 0.f);
                *(float4*)&g_h[(size_t)gm * DD + n] = v;
            }
        } else {
            uint2 hi, lo;
            split4(v, hi, lo);
            *(uint2*)&Eh[r * BLD + n] = hi;
            *(uint2*)&El[r * BLD + n] = lo;
            if (gm < NN) {
                if (lead >= 0) {
                    size_t o = (size_t)lead + (size_t)gm * DD + n;
                    if (out_vec) {
                        *(float4*)&out[o] = v;
                    } else {
                        out[o + 0] = v.x; out[o + 1] = v.y;
                        out[o + 2] = v.z; out[o + 3] = v.w;
                    }
                } else {
                    *(float4*)&g_emb[(size_t)gm * DD + n] = v;
                }
            }
        }
    }

    // ---------------- fused decoder (A from smem) + BCE loss + final (CFG==1) ----
    if (CFG == 1) {
        // store both prestaged B chunks into Bs buf0/buf1
        #pragma unroll
        for (int c = 0; c < 2; c++)
            #pragma unroll
            for (int hl = 0; hl < 2; hl++) {
                __nv_bfloat16* B = bs_ptr(sdyn, c, hl);
                #pragma unroll
                for (int half = 0; half < 2; half++) {
                    int id = tid + half * 512;
                    int k = id >> 4, c16 = id & 15;
                    ((uint4*)&B[k * BLD])[c16] = pb[c * 4 + hl * 2 + half];
                }
            }
        #pragma unroll
        for (int mt = 0; mt < 2; mt++)
            #pragma unroll
            for (int nt = 0; nt < 2; nt++) wmma::fill_fragment(acc[mt][nt], 0.f);
        __syncthreads();   // emb image + B tiles visible

        mma_dec(sdyn, 0, 0, acc, warp_m, warp_n);
        mma_dec(sdyn, 1, 1, acc, warp_m, warp_n);
        __syncthreads();

        store_frags(buf, acc, warp_m, warp_n);
        __syncthreads();
        float lp = 0.f, ln = 0.f;
        #pragma unroll
        for (int it = 0; it < 8; it++) {
            int id = tid + it * 512;
            int r = id >> 5, n = (id & 31) * 4;
            int gm = m0 + r;
            if (gm < NN) {
                float4 v = *(float4*)&buf[r * BLD + n];
                bool pos = g_yb[gm] != 0;
                float vv[4] = {v.x, v.y, v.z, v.w};
                #pragma unroll
                for (int j = 0; j < 4; j++) {
                    float t2 = pos ? -vv[j] : vv[j];
                    float sp = fmaxf(t2, 0.f) + log1pf(expf(-fabsf(t2)));
                    if (pos) lp += sp; else ln += sp;
                }
            }
        }
        #pragma unroll
        for (int o = 16; o; o >>= 1) {
            lp += __shfl_down_sync(0xffffffffu, lp, o);
            ln += __shfl_down_sync(0xffffffffu, ln, o);
        }
        if ((tid & 31) == 0) {
            atomicAdd(&g_lp, lp);
            atomicAdd(&g_ln, ln);
        }

        __syncthreads();
        if (tid == 0) {
            __threadfence();
            int old = atomicAdd(&g_done, 1);
            if (old == (int)gridDim.x - 1) {
                __threadfence();
                float lpv = *((volatile float*)&g_lp);
                float lnv = *((volatile float*)&g_ln);
                int   np  = *((volatile int*)&g_npos);
                float l2 = lpv / (fmaxf((float)np, 1.f) * (float)DD);
                float l1 = lnv / (fmaxf((float)(NN - np), 1.f) * (float)DD);
                float loss = l1 + l2;
                if (lead > 0) {
                    for (int i = 0; i < lead && i < 16; i++) out[i] = loss;
                } else if (out_size > 0) {
                    out[0] = loss;
                }
                g_lp = 0.f; g_ln = 0.f; g_npos = 0; g_done = 0;
            }
        }
    }
}

__global__ void k_copy(float* __restrict__ out, int out_size) {
    int i = blockIdx.x * blockDim.x + threadIdx.x;
    if (i < out_size && i < OUT_ELEMS) out[i] = g_emb[i];
}

// ---------------- launch ----------------
extern "C" void kernel_launch(void* const* d_in, const int* in_sizes, int n_in,
                              void* d_out, int out_size) {
    const float* x = nullptr;
    const void*  edge = nullptr;
    const void*  yv = nullptr;
    const float* Ws[5] = {nullptr, nullptr, nullptr, nullptr, nullptr};
    const float* bs[2] = {nullptr, nullptr};
    int wi = 0, bi = 0;
    for (int i = 0; i < n_in; i++) {
        int sz = in_sizes[i];
        if (sz == NN * DD && !x) x = (const float*)d_in[i];
        else if (sz == 2 * NE && !edge) edge = d_in[i];
        else if (sz == NN && !yv) yv = d_in[i];
        else if (sz == DD * DD && wi < 5) Ws[wi++] = (const float*)d_in[i];
        else if (sz == DD && bi < 2) bs[bi++] = (const float*)d_in[i];
    }
    const float* b1l = bs[0];
    const float* b2l = bs[1];
    float* out = (float*)d_out;
    int lead = out_size - OUT_ELEMS;

    cudaFuncSetAttribute(k_gemm<0>, cudaFuncAttributeMaxDynamicSharedMemorySize, SMEM_G0);
    cudaFuncSetAttribute(k_gemm<1>, cudaFuncAttributeMaxDynamicSharedMemorySize, SMEM_G1);

    k_prep <<<EDGE_BLOCKS, 256>>>(yv, edge, Ws[0], Ws[1], Ws[2], Ws[3], Ws[4]);
    k_scan <<<SCAN_B, 256>>>();
    k_fill <<<EDGE_BLOCKS, 256>>>(edge);

    // layer 1
    k_mean<0><<<(NN + 7) / 8, 256>>>(x);
    k_gemm<0><<<GEMM_BLOCKS, 512, SMEM_G0>>>(x, b1l, out, lead, out_size);

    // layer 2 + fused decoder + loss + final
    k_mean<1><<<(NN + 7) / 8, 256>>>(nullptr);
    k_gemm<1><<<GEMM_BLOCKS, 512, SMEM_G1>>>(nullptr, b2l, out, lead, out_size);

    if (lead < 0) k_copy<<<(OUT_ELEMS + 255) / 256, 256>>>(out, out_size);
}